// round 10
// baseline (speedup 1.0000x reference)
#include <cuda_runtime.h>
#include <cuda_bf16.h>
#include <cuda_fp8.h>
#include <cstdint>
#include <cstddef>

// ---------------------------------------------------------------------------
// d[n,c] = ||x_n||^2 + ||p_c||^2 - 2 * <x_n, p_c>
// x: [16384,1024] f32, p: [4096,1024] f32, out: [16384,4096] f32
//
// fp8 e4m3 mma.sync m16n8k32 (fp32 acc), mean-split hardening (p = 0.5 + r).
// R9 profile: tensor=58.7%, idle = LDSM phases + mbarrier traffic under the
// 128-reg 2-CTA cap. Now: ONE 512-thread CTA (tile 128x256, 16 warps/SM,
// 255-reg budget), fragment double-buffering across k32 steps, warp-leader
// EMPTY arrives released before the last mma batch, cp.async.bulk stage fill
// from pre-tiled pre-swizzled fp8 blocks.
// ---------------------------------------------------------------------------

static constexpr int N_ROWS = 16384;
static constexpr int C_ROWS = 4096;
static constexpr int DDIM   = 1024;

static constexpr int TILE_M = 128;
static constexpr int TILE_N = 256;
static constexpr int TILE_K = 128;                      // 128 fp8 = 128 B/row
static constexpr int K_TILES = DDIM / TILE_K;           // 8
static constexpr int STAGES  = 3;

static constexpr int A_BLOCK = TILE_M * TILE_K;         // 16384
static constexpr int B_BLOCK = TILE_N * TILE_K;         // 32768
static constexpr int STAGE_BYTES = A_BLOCK + B_BLOCK;   // 49152
static constexpr unsigned SMEM_DYN = STAGES * STAGE_BYTES + 1024;  // 148480

// ---------------- device scratch (allocations are forbidden) ---------------
// g_A: [M_TILES][K_TILES][128x128B swizzled]; g_B: [N_TILES][K_TILES][256x128B]
__device__ __align__(128) uint8_t g_A[(size_t)N_ROWS * DDIM];   // 16 MB fp8
__device__ __align__(128) uint8_t g_B[(size_t)C_ROWS * DDIM];   //  4 MB fp8
__device__ float g_xc[N_ROWS];    // ||x||^2 - sum(x)
__device__ float g_psq[C_ROWS];   // ||p||^2 exact
__device__ float g_sx[N_ROWS];    // 2 * amax_x / 448
__device__ float g_sp[C_ROWS];    //     amax_r / 448

// ------------------------------ helpers ------------------------------------
__device__ __forceinline__ uint32_t s2u(const void* p) {
    return (uint32_t)__cvta_generic_to_shared(p);
}
__device__ __forceinline__ uint32_t swz(uint32_t o) { return o ^ ((o >> 3) & 0x70u); }

__device__ __forceinline__ void mbar_init(uint32_t a, uint32_t n) {
    asm volatile("mbarrier.init.shared.b64 [%0], %1;" :: "r"(a), "r"(n) : "memory");
}
__device__ __forceinline__ void mbar_expect(uint32_t a, uint32_t tx) {
    asm volatile("mbarrier.arrive.expect_tx.shared.b64 _, [%0], %1;"
                 :: "r"(a), "r"(tx) : "memory");
}
__device__ __forceinline__ void mbar_arrive(uint32_t a) {
    asm volatile("mbarrier.arrive.shared.b64 _, [%0];" :: "r"(a) : "memory");
}
__device__ __forceinline__ void mbar_wait(uint32_t a, uint32_t phase) {
    asm volatile(
        "{\n\t.reg .pred P;\n"
        "W%=:\n\t"
        "mbarrier.try_wait.parity.acquire.cta.shared::cta.b64 P, [%0], %1, 0x989680;\n\t"
        "@P bra D%=;\n\t"
        "bra W%=;\n"
        "D%=:\n\t}"
        :: "r"(a), "r"(phase) : "memory");
}
__device__ __forceinline__ void bulk_g2s(uint32_t dst, const void* src,
                                         uint32_t bytes, uint32_t bar) {
    asm volatile(
        "cp.async.bulk.shared::cluster.global.mbarrier::complete_tx::bytes "
        "[%0], [%1], %2, [%3];"
        :: "r"(dst), "l"(src), "r"(bytes), "r"(bar) : "memory");
}
__device__ __forceinline__ void ldm_x4(uint32_t* r, uint32_t addr) {
    asm volatile("ldmatrix.sync.aligned.m8n8.x4.shared.b16 {%0,%1,%2,%3}, [%4];"
                 : "=r"(r[0]), "=r"(r[1]), "=r"(r[2]), "=r"(r[3]) : "r"(addr));
}
__device__ __forceinline__ void mma16832(float* c, const uint32_t* a,
                                         uint32_t b0, uint32_t b1) {
    asm volatile(
        "mma.sync.aligned.m16n8k32.row.col.f32.e4m3.e4m3.f32 "
        "{%0,%1,%2,%3}, {%4,%5,%6,%7}, {%8,%9}, {%0,%1,%2,%3};"
        : "+f"(c[0]), "+f"(c[1]), "+f"(c[2]), "+f"(c[3])
        : "r"(a[0]), "r"(a[1]), "r"(a[2]), "r"(a[3]), "r"(b0), "r"(b1));
}
__device__ __forceinline__ uint32_t qfp8x4(float4 f, float q) {
    __nv_fp8x4_e4m3 v(make_float4(f.x * q, f.y * q, f.z * q, f.w * q));
    return *reinterpret_cast<uint32_t*>(&v);
}

// ------ pre-pass: f32 -> scaled e4m3, TILED+SWIZZLED blocks + norms --------
// x rows -> 128-row A blocks; p rows (r = p-0.5) -> 256-row B blocks.
__global__ void __launch_bounds__(128)
convq_kernel(const float* __restrict__ xsrc, const float* __restrict__ psrc) {
    const bool isx = (blockIdx.x < N_ROWS / 4);
    const int row  = (isx ? blockIdx.x : blockIdx.x - N_ROWS / 4) * 4
                   + (threadIdx.x >> 5);
    const int lane = threadIdx.x & 31;
    const float* src = isx ? xsrc : psrc;
    const float4* xr = reinterpret_cast<const float4*>(src + (size_t)row * DDIM);

    float4 f[2][4];
    float ss = 0.f, sm = 0.f, am = 0.f;
#pragma unroll
    for (int h = 0; h < 2; h++) {
        const int c = lane + h * 32;               // 16-elem chunk id (0..63)
#pragma unroll
        for (int j = 0; j < 4; j++) {
            float4 v = xr[c * 4 + j];
            ss += v.x * v.x + v.y * v.y + v.z * v.z + v.w * v.w;
            if (isx) {
                sm += v.x + v.y + v.z + v.w;
            } else {
                v.x -= 0.5f; v.y -= 0.5f; v.z -= 0.5f; v.w -= 0.5f;
            }
            f[h][j] = v;
            am = fmaxf(am, fmaxf(fmaxf(fabsf(v.x), fabsf(v.y)),
                                 fmaxf(fabsf(v.z), fabsf(v.w))));
        }
    }
#pragma unroll
    for (int o = 16; o; o >>= 1) {
        ss += __shfl_xor_sync(0xffffffffu, ss, o);
        am = fmaxf(am, __shfl_xor_sync(0xffffffffu, am, o));
        sm += __shfl_xor_sync(0xffffffffu, sm, o);
    }
    am = fmaxf(am, 1e-30f);
    const float q = 448.f / am;

    const int blk_rows_log2 = isx ? 7 : 8;
    const int rt = row >> blk_rows_log2;
    const int rr = row & ((1 << blk_rows_log2) - 1);
    const int blk_bytes = isx ? A_BLOCK : B_BLOCK;
    uint8_t* base = (isx ? g_A : g_B)
                  + (size_t)rt * K_TILES * blk_bytes;
#pragma unroll
    for (int h = 0; h < 2; h++) {
        const int c  = lane + h * 32;
        const int kt = c >> 3;                     // which 128-elem K tile
        const int cu = (c & 7) * 16;               // byte col within 128B row
        uint4 v;
        v.x = qfp8x4(f[h][0], q); v.y = qfp8x4(f[h][1], q);
        v.z = qfp8x4(f[h][2], q); v.w = qfp8x4(f[h][3], q);
        *reinterpret_cast<uint4*>(base + (size_t)kt * blk_bytes
                                  + swz((uint32_t)(rr * 128 + cu))) = v;
    }
    if (lane == 0) {
        if (isx) {
            g_xc[row] = ss - sm;
            g_sx[row] = 2.f * am * (1.f / 448.f);
        } else {
            g_psq[row] = ss;
            g_sp[row]  = am * (1.f / 448.f);
        }
    }
}

// --------------------------- main GEMM kernel ------------------------------
// CTA: 512 threads = 16 warps (4M x 4N); warp tile 32x64; 1 CTA/SM.
__global__ void __launch_bounds__(512, 1)
gemm_kernel(float* __restrict__ out) {
    extern __shared__ char smem[];
    __shared__ __align__(8) uint64_t s_bar[2 * STAGES];   // FULL[3], EMPTY[3]

    const uint32_t sbase = (s2u(smem) + 1023u) & ~1023u;
    const uint32_t FULL  = s2u(s_bar);
    const uint32_t EMPTY = FULL + STAGES * 8;

    const int tid  = threadIdx.x;
    const int wid  = tid >> 5;
    const int lane = tid & 31;
    const int wm = (wid & 3) * 32;                 // warp M offset
    const int wn = (wid >> 2) * 64;                // warp N offset

    const uint8_t* Ag = g_A + (size_t)blockIdx.x * K_TILES * A_BLOCK;
    const uint8_t* Bg = g_B + (size_t)blockIdx.y * K_TILES * B_BLOCK;

    if (tid == 0) {
#pragma unroll
        for (int s = 0; s < STAGES; s++) {
            mbar_init(FULL + s * 8, 1);            // tx-based completion
            mbar_init(EMPTY + s * 8, 16);          // one arrive per warp
        }
    }
    __syncthreads();

    if (tid == 0) {
#pragma unroll
        for (int s = 0; s < STAGES - 1; s++) {
            const uint32_t fb  = FULL + s * 8;
            const uint32_t dst = sbase + s * STAGE_BYTES;
            mbar_expect(fb, STAGE_BYTES);
            bulk_g2s(dst,           Ag + (size_t)s * A_BLOCK, A_BLOCK, fb);
            bulk_g2s(dst + A_BLOCK, Bg + (size_t)s * B_BLOCK, B_BLOCK, fb);
        }
    }

    float acc[2][8][4];
#pragma unroll
    for (int i = 0; i < 2; i++)
#pragma unroll
        for (int j = 0; j < 8; j++)
#pragma unroll
            for (int r = 0; r < 4; r++) acc[i][j][r] = 0.f;

    const int lrow = lane & 15;
    const int lkb  = (lane >> 4) * 16;

    // double-buffered fragments
    uint32_t a[2][2][4], b[2][4][4];

    int pst = STAGES - 1, pph = 1;                 // producer cursor
    int cst = 0, cph = 0;                          // consumer cursor

    for (int kt = 0; kt < K_TILES; kt++) {
        // ---- producer: refill stage for kt+STAGES-1 ----------------------
        if (tid == 0 && kt + STAGES - 1 < K_TILES) {
            const int kf = kt + STAGES - 1;
            mbar_wait(EMPTY + pst * 8, (uint32_t)pph);
            const uint32_t fb  = FULL + pst * 8;
            const uint32_t dst = sbase + pst * STAGE_BYTES;
            mbar_expect(fb, STAGE_BYTES);
            bulk_g2s(dst,           Ag + (size_t)kf * A_BLOCK, A_BLOCK, fb);
            bulk_g2s(dst + A_BLOCK, Bg + (size_t)kf * B_BLOCK, B_BLOCK, fb);
            if (++pst == STAGES) { pst = 0; pph ^= 1; }
        }

        // ---- consumer --------------------------------------------------
        mbar_wait(FULL + cst * 8, (uint32_t)cph);
        const uint32_t sA = sbase + cst * STAGE_BYTES;
        const uint32_t sB = sA + A_BLOCK;

        // prefetch kk=0 fragments
        {
            const int kc = lkb;
#pragma unroll
            for (int mi = 0; mi < 2; mi++)
                ldm_x4(a[0][mi], sA + swz((uint32_t)((wm + mi * 16 + lrow) * 128 + kc)));
#pragma unroll
            for (int nj = 0; nj < 4; nj++)
                ldm_x4(b[0][nj], sB + swz((uint32_t)((wn + nj * 16 + lrow) * 128 + kc)));
        }

#pragma unroll
        for (int kk = 0; kk < 4; kk++) {
            const int cur = kk & 1;
            if (kk < 3) {                          // prefetch next k32 step
                const int nxt = cur ^ 1;
                const int kc  = (kk + 1) * 32 + lkb;
#pragma unroll
                for (int mi = 0; mi < 2; mi++)
                    ldm_x4(a[nxt][mi],
                           sA + swz((uint32_t)((wm + mi * 16 + lrow) * 128 + kc)));
#pragma unroll
                for (int nj = 0; nj < 4; nj++)
                    ldm_x4(b[nxt][nj],
                           sB + swz((uint32_t)((wn + nj * 16 + lrow) * 128 + kc)));
            } else if (lane == 0) {
                mbar_arrive(EMPTY + cst * 8);      // all reads of stage issued
            }
#pragma unroll
            for (int mi = 0; mi < 2; mi++) {
#pragma unroll
                for (int nj = 0; nj < 4; nj++) {
                    mma16832(acc[mi][2 * nj + 0], a[cur][mi],
                             b[cur][nj][0], b[cur][nj][2]);
                    mma16832(acc[mi][2 * nj + 1], a[cur][mi],
                             b[cur][nj][1], b[cur][nj][3]);
                }
            }
        }
        if (++cst == STAGES) { cst = 0; cph ^= 1; }
    }

    // ---- fused dequant epilogue: out = xc + psq - sx*sp*acc  (x2 in sx) ----
    const int m0 = blockIdx.x * TILE_M;
    const int n0 = blockIdx.y * TILE_N;
    const int tr = lane >> 2;
    const int tc = (lane & 3) * 2;
#pragma unroll
    for (int mi = 0; mi < 2; mi++) {
        const int gm0 = m0 + wm + mi * 16 + tr;
        const float xc0 = g_xc[gm0],     sx0 = g_sx[gm0];
        const float xc1 = g_xc[gm0 + 8], sx1 = g_sx[gm0 + 8];
        float* o0 = out + (size_t)gm0 * C_ROWS + n0 + wn;
        float* o1 = o0 + (size_t)8 * C_ROWS;
#pragma unroll
        for (int ni = 0; ni < 8; ni++) {
            const int gc = n0 + wn + ni * 8 + tc;
            const float pq0 = __ldg(g_psq + gc),     sp0 = __ldg(g_sp + gc);
            const float pq1 = __ldg(g_psq + gc + 1), sp1 = __ldg(g_sp + gc + 1);
            float2 r0, r1;
            r0.x = fmaf(-sx0 * sp0, acc[mi][ni][0], xc0 + pq0);
            r0.y = fmaf(-sx0 * sp1, acc[mi][ni][1], xc0 + pq1);
            r1.x = fmaf(-sx1 * sp0, acc[mi][ni][2], xc1 + pq0);
            r1.y = fmaf(-sx1 * sp1, acc[mi][ni][3], xc1 + pq1);
            *reinterpret_cast<float2*>(o0 + ni * 8 + tc) = r0;
            *reinterpret_cast<float2*>(o1 + ni * 8 + tc) = r1;
        }
    }
}

// ------------------------------- launch ------------------------------------
extern "C" void kernel_launch(void* const* d_in, const int* in_sizes, int n_in,
                              void* d_out, int out_size) {
    const float* x = (const float*)d_in[0];       // [16384, 1024]
    const float* p = (const float*)d_in[1];       // [4096, 1024]
    float* out = (float*)d_out;                   // [16384, 4096]

    cudaFuncSetAttribute(gemm_kernel,
                         cudaFuncAttributeMaxDynamicSharedMemorySize, SMEM_DYN);

    convq_kernel<<<(N_ROWS + C_ROWS) / 4, 128>>>(x, p);
    gemm_kernel<<<dim3(N_ROWS / TILE_M, C_ROWS / TILE_N), 512, SMEM_DYN>>>(out);
}

// round 11
// speedup vs baseline: 1.0992x; 1.0992x over previous
#include <cuda_runtime.h>
#include <cuda_bf16.h>
#include <cuda_fp8.h>
#include <cstdint>
#include <cstddef>

// ---------------------------------------------------------------------------
// d[n,c] = ||x_n||^2 + ||p_c||^2 - 2 * <x_n, p_c>
// x: [16384,1024] f32, p: [4096,1024] f32, out: [16384,4096] f32
//
// fp8 e4m3 mma.sync m16n8k32 (fp32 acc), mean-split hardening (p = 0.5 + r).
// R9 base (2 CTA x 256thr, 3-stage cp.async.bulk pipeline, pre-tiled fp8)
// + per-warp kk rotation (desyncs LDSM bursts across warps of an SMSP so the
// tensor pipe never drains at ldm phases) + early warp-leader EMPTY arrive.
// ---------------------------------------------------------------------------

static constexpr int N_ROWS = 16384;
static constexpr int C_ROWS = 4096;
static constexpr int DDIM   = 1024;

static constexpr int TILE_M = 128;
static constexpr int TILE_N = 128;
static constexpr int TILE_K = 128;                      // 128 fp8 = 128 B/row
static constexpr int K_TILES = DDIM / TILE_K;           // 8
static constexpr int STAGES  = 3;

static constexpr int BLOCK_BYTES  = TILE_M * TILE_K;    // 16384
static constexpr int STAGE_BYTES  = 2 * BLOCK_BYTES;    // 32768
static constexpr unsigned SMEM_DYN = STAGES * STAGE_BYTES + 1024;

// ---------------- device scratch (allocations are forbidden) ---------------
__device__ __align__(128) uint8_t g_A[(size_t)N_ROWS * DDIM];   // 16 MB fp8
__device__ __align__(128) uint8_t g_B[(size_t)C_ROWS * DDIM];   //  4 MB fp8
__device__ float g_xc[N_ROWS];    // ||x||^2 - sum(x)
__device__ float g_psq[C_ROWS];   // ||p||^2 exact
__device__ float g_sx[N_ROWS];    // 2 * amax_x / 448
__device__ float g_sp[C_ROWS];    //     amax_r / 448

// ------------------------------ helpers ------------------------------------
__device__ __forceinline__ uint32_t s2u(const void* p) {
    return (uint32_t)__cvta_generic_to_shared(p);
}
__device__ __forceinline__ uint32_t swz(uint32_t o) { return o ^ ((o >> 3) & 0x70u); }

__device__ __forceinline__ void mbar_init(uint32_t a, uint32_t n) {
    asm volatile("mbarrier.init.shared.b64 [%0], %1;" :: "r"(a), "r"(n) : "memory");
}
__device__ __forceinline__ void mbar_expect(uint32_t a, uint32_t tx) {
    asm volatile("mbarrier.arrive.expect_tx.shared.b64 _, [%0], %1;"
                 :: "r"(a), "r"(tx) : "memory");
}
__device__ __forceinline__ void mbar_arrive(uint32_t a) {
    asm volatile("mbarrier.arrive.shared.b64 _, [%0];" :: "r"(a) : "memory");
}
__device__ __forceinline__ void mbar_wait(uint32_t a, uint32_t phase) {
    asm volatile(
        "{\n\t.reg .pred P;\n"
        "W%=:\n\t"
        "mbarrier.try_wait.parity.acquire.cta.shared::cta.b64 P, [%0], %1, 0x989680;\n\t"
        "@P bra D%=;\n\t"
        "bra W%=;\n"
        "D%=:\n\t}"
        :: "r"(a), "r"(phase) : "memory");
}
__device__ __forceinline__ void bulk_g2s(uint32_t dst, const void* src,
                                         uint32_t bytes, uint32_t bar) {
    asm volatile(
        "cp.async.bulk.shared::cluster.global.mbarrier::complete_tx::bytes "
        "[%0], [%1], %2, [%3];"
        :: "r"(dst), "l"(src), "r"(bytes), "r"(bar) : "memory");
}
__device__ __forceinline__ void ldm_x4(uint32_t* r, uint32_t addr) {
    asm volatile("ldmatrix.sync.aligned.m8n8.x4.shared.b16 {%0,%1,%2,%3}, [%4];"
                 : "=r"(r[0]), "=r"(r[1]), "=r"(r[2]), "=r"(r[3]) : "r"(addr));
}
__device__ __forceinline__ void mma16832(float* c, const uint32_t* a,
                                         uint32_t b0, uint32_t b1) {
    asm volatile(
        "mma.sync.aligned.m16n8k32.row.col.f32.e4m3.e4m3.f32 "
        "{%0,%1,%2,%3}, {%4,%5,%6,%7}, {%8,%9}, {%0,%1,%2,%3};"
        : "+f"(c[0]), "+f"(c[1]), "+f"(c[2]), "+f"(c[3])
        : "r"(a[0]), "r"(a[1]), "r"(a[2]), "r"(a[3]), "r"(b0), "r"(b1));
}
__device__ __forceinline__ uint32_t qfp8x4(float4 f, float q) {
    __nv_fp8x4_e4m3 v(make_float4(f.x * q, f.y * q, f.z * q, f.w * q));
    return *reinterpret_cast<uint32_t*>(&v);
}

// ------ pre-pass: f32 -> scaled e4m3, TILED+SWIZZLED blocks + norms --------
__global__ void __launch_bounds__(128)
convq_kernel(const float* __restrict__ xsrc, const float* __restrict__ psrc) {
    const bool isx = (blockIdx.x < N_ROWS / 4);
    const int row  = (isx ? blockIdx.x : blockIdx.x - N_ROWS / 4) * 4
                   + (threadIdx.x >> 5);
    const int lane = threadIdx.x & 31;
    const float* src = isx ? xsrc : psrc;
    uint8_t* dst     = isx ? g_A : g_B;
    const float4* xr = reinterpret_cast<const float4*>(src + (size_t)row * DDIM);

    float4 f[2][4];
    float ss = 0.f, sm = 0.f, am = 0.f;
#pragma unroll
    for (int h = 0; h < 2; h++) {
        const int c = lane + h * 32;
#pragma unroll
        for (int j = 0; j < 4; j++) {
            float4 v = xr[c * 4 + j];
            ss += v.x * v.x + v.y * v.y + v.z * v.z + v.w * v.w;
            if (isx) {
                sm += v.x + v.y + v.z + v.w;
            } else {
                v.x -= 0.5f; v.y -= 0.5f; v.z -= 0.5f; v.w -= 0.5f;
            }
            f[h][j] = v;
            am = fmaxf(am, fmaxf(fmaxf(fabsf(v.x), fabsf(v.y)),
                                 fmaxf(fabsf(v.z), fabsf(v.w))));
        }
    }
#pragma unroll
    for (int o = 16; o; o >>= 1) {
        ss += __shfl_xor_sync(0xffffffffu, ss, o);
        am = fmaxf(am, __shfl_xor_sync(0xffffffffu, am, o));
        sm += __shfl_xor_sync(0xffffffffu, sm, o);
    }
    am = fmaxf(am, 1e-30f);
    const float q = 448.f / am;

    const int rt = row >> 7, rr = row & 127;
#pragma unroll
    for (int h = 0; h < 2; h++) {
        const int c  = lane + h * 32;
        const int kt = c >> 3;
        const int cu = (c & 7) * 16;
        uint4 v;
        v.x = qfp8x4(f[h][0], q); v.y = qfp8x4(f[h][1], q);
        v.z = qfp8x4(f[h][2], q); v.w = qfp8x4(f[h][3], q);
        uint8_t* blk = dst + ((size_t)rt * K_TILES + kt) * BLOCK_BYTES;
        *reinterpret_cast<uint4*>(blk + swz((uint32_t)(rr * 128 + cu))) = v;
    }
    if (lane == 0) {
        if (isx) {
            g_xc[row] = ss - sm;
            g_sx[row] = 2.f * am * (1.f / 448.f);
        } else {
            g_psq[row] = ss;
            g_sp[row]  = am * (1.f / 448.f);
        }
    }
}

// --------------------------- main GEMM kernel ------------------------------
// CTA: 256 threads = 8 warps (2M x 4N); warp tile 64x32; 2 CTAs/SM.
__global__ void __launch_bounds__(256, 2)
gemm_kernel(float* __restrict__ out) {
    extern __shared__ char smem[];
    __shared__ __align__(8) uint64_t s_bar[2 * STAGES];   // FULL[3], EMPTY[3]

    const uint32_t sbase = (s2u(smem) + 1023u) & ~1023u;
    const uint32_t FULL  = s2u(s_bar);
    const uint32_t EMPTY = FULL + STAGES * 8;

    const int tid  = threadIdx.x;
    const int wid  = tid >> 5;
    const int lane = tid & 31;
    const int wm = (wid & 1) * 64;
    const int wn = (wid >> 1) * 32;

    const uint8_t* Ag = g_A + (size_t)blockIdx.x * K_TILES * BLOCK_BYTES;
    const uint8_t* Bg = g_B + (size_t)blockIdx.y * K_TILES * BLOCK_BYTES;

    if (tid == 0) {
#pragma unroll
        for (int s = 0; s < STAGES; s++) {
            mbar_init(FULL + s * 8, 1);            // tx-based completion
            mbar_init(EMPTY + s * 8, 8);           // one arrive per warp
        }
    }
    __syncthreads();

    if (tid == 0) {
#pragma unroll
        for (int s = 0; s < STAGES - 1; s++) {
            const uint32_t fb  = FULL + s * 8;
            const uint32_t dst = sbase + s * STAGE_BYTES;
            mbar_expect(fb, STAGE_BYTES);
            bulk_g2s(dst,               Ag + (size_t)s * BLOCK_BYTES, BLOCK_BYTES, fb);
            bulk_g2s(dst + BLOCK_BYTES, Bg + (size_t)s * BLOCK_BYTES, BLOCK_BYTES, fb);
        }
    }

    float acc[4][4][4];
#pragma unroll
    for (int i = 0; i < 4; i++)
#pragma unroll
        for (int j = 0; j < 4; j++)
#pragma unroll
            for (int r = 0; r < 4; r++) acc[i][j][r] = 0.f;

    const int lrow = lane & 15;
    const int lkb  = (lane >> 4) * 16;
    const int krot = wid & 3;                      // per-warp kk rotation

    int pst = STAGES - 1, pph = 1;                 // producer cursor
    int cst = 0, cph = 0;                          // consumer cursor

    for (int kt = 0; kt < K_TILES; kt++) {
        // ---- producer: refill stage for kt+STAGES-1 ----------------------
        if (tid == 0 && kt + STAGES - 1 < K_TILES) {
            const int kf = kt + STAGES - 1;
            mbar_wait(EMPTY + pst * 8, (uint32_t)pph);
            const uint32_t fb  = FULL + pst * 8;
            const uint32_t dst = sbase + pst * STAGE_BYTES;
            mbar_expect(fb, STAGE_BYTES);
            bulk_g2s(dst,               Ag + (size_t)kf * BLOCK_BYTES, BLOCK_BYTES, fb);
            bulk_g2s(dst + BLOCK_BYTES, Bg + (size_t)kf * BLOCK_BYTES, BLOCK_BYTES, fb);
            if (++pst == STAGES) { pst = 0; pph ^= 1; }
        }

        // ---- consumer: 4 x k32 MMA steps, kk order rotated per warp ------
        mbar_wait(FULL + cst * 8, (uint32_t)cph);
        const uint32_t sA = sbase + cst * STAGE_BYTES;
        const uint32_t sB = sA + BLOCK_BYTES;

#pragma unroll
        for (int kk4 = 0; kk4 < 4; kk4++) {
            const int kk = (kk4 + krot) & 3;       // acc order-independent
            const int kc = kk * 32 + lkb;
            uint32_t a[4][4], b[2][4];
#pragma unroll
            for (int mi = 0; mi < 4; mi++)
                ldm_x4(a[mi], sA + swz((uint32_t)((wm + mi * 16 + lrow) * 128 + kc)));
#pragma unroll
            for (int nj = 0; nj < 2; nj++)
                ldm_x4(b[nj], sB + swz((uint32_t)((wn + nj * 16 + lrow) * 128 + kc)));

            if (kk4 == 3 && lane == 0)             // all smem reads issued
                mbar_arrive(EMPTY + cst * 8);

#pragma unroll
            for (int mi = 0; mi < 4; mi++) {
#pragma unroll
                for (int nj = 0; nj < 2; nj++) {
                    mma16832(acc[mi][2 * nj + 0], a[mi], b[nj][0], b[nj][2]);
                    mma16832(acc[mi][2 * nj + 1], a[mi], b[nj][1], b[nj][3]);
                }
            }
        }
        if (++cst == STAGES) { cst = 0; cph ^= 1; }
    }

    // ---- fused dequant epilogue: out = xc + psq - sx*sp*acc  (x2 in sx) ----
    const int m0 = blockIdx.x * TILE_M;
    const int n0 = blockIdx.y * TILE_N;
    const int tr = lane >> 2;
    const int tc = (lane & 3) * 2;
#pragma unroll
    for (int mi = 0; mi < 4; mi++) {
        const int gm0 = m0 + wm + mi * 16 + tr;
        const float xc0 = g_xc[gm0],     sx0 = g_sx[gm0];
        const float xc1 = g_xc[gm0 + 8], sx1 = g_sx[gm0 + 8];
        float* o0 = out + (size_t)gm0 * C_ROWS + n0 + wn;
        float* o1 = o0 + (size_t)8 * C_ROWS;
#pragma unroll
        for (int ni = 0; ni < 4; ni++) {
            const int gc = n0 + wn + ni * 8 + tc;
            const float pq0 = __ldg(g_psq + gc),     sp0 = __ldg(g_sp + gc);
            const float pq1 = __ldg(g_psq + gc + 1), sp1 = __ldg(g_sp + gc + 1);
            float2 r0, r1;
            r0.x = fmaf(-sx0 * sp0, acc[mi][ni][0], xc0 + pq0);
            r0.y = fmaf(-sx0 * sp1, acc[mi][ni][1], xc0 + pq1);
            r1.x = fmaf(-sx1 * sp0, acc[mi][ni][2], xc1 + pq0);
            r1.y = fmaf(-sx1 * sp1, acc[mi][ni][3], xc1 + pq1);
            *reinterpret_cast<float2*>(o0 + ni * 8 + tc) = r0;
            *reinterpret_cast<float2*>(o1 + ni * 8 + tc) = r1;
        }
    }
}

// ------------------------------- launch ------------------------------------
extern "C" void kernel_launch(void* const* d_in, const int* in_sizes, int n_in,
                              void* d_out, int out_size) {
    const float* x = (const float*)d_in[0];       // [16384, 1024]
    const float* p = (const float*)d_in[1];       // [4096, 1024]
    float* out = (float*)d_out;                   // [16384, 4096]

    cudaFuncSetAttribute(gemm_kernel,
                         cudaFuncAttributeMaxDynamicSharedMemorySize, SMEM_DYN);

    convq_kernel<<<(N_ROWS + C_ROWS) / 4, 128>>>(x, p);
    gemm_kernel<<<dim3(N_ROWS / TILE_M, C_ROWS / TILE_N), 256, SMEM_DYN>>>(out);
}

// round 12
// speedup vs baseline: 1.2790x; 1.1636x over previous
#include <cuda_runtime.h>
#include <cuda_bf16.h>
#include <cuda_fp8.h>
#include <cstdint>
#include <cstddef>

// ---------------------------------------------------------------------------
// d[n,c] = ||x_n||^2 + ||p_c||^2 - 2 * <x_n, p_c>
// x: [16384,1024] f32, p: [4096,1024] f32, out: [16384,4096] f32
//
// fp8 e4m3 mma.sync m16n8k32 (fp32 acc), mean-split hardening (p = 0.5 + r).
// R11 analysis: crossbar (1536cyc) + tensor (2048cyc) SERIALIZE per kt
// because asm-volatile order is [6 LDSM][16 MMA] and warps are phase-locked.
// Now: hand-interleaved stream  [ldm a(i+1)][4 mma a(i)]  + B fragment
// double-buffer across k32 steps -> LDSM hides under MMA. +8 regs only.
// ---------------------------------------------------------------------------

static constexpr int N_ROWS = 16384;
static constexpr int C_ROWS = 4096;
static constexpr int DDIM   = 1024;

static constexpr int TILE_M = 128;
static constexpr int TILE_N = 128;
static constexpr int TILE_K = 128;                      // 128 fp8 = 128 B/row
static constexpr int K_TILES = DDIM / TILE_K;           // 8
static constexpr int STAGES  = 3;

static constexpr int BLOCK_BYTES  = TILE_M * TILE_K;    // 16384
static constexpr int STAGE_BYTES  = 2 * BLOCK_BYTES;    // 32768
static constexpr unsigned SMEM_DYN = STAGES * STAGE_BYTES + 1024;

// ---------------- device scratch (allocations are forbidden) ---------------
__device__ __align__(128) uint8_t g_A[(size_t)N_ROWS * DDIM];   // 16 MB fp8
__device__ __align__(128) uint8_t g_B[(size_t)C_ROWS * DDIM];   //  4 MB fp8
__device__ float g_xc[N_ROWS];    // ||x||^2 - sum(x)
__device__ float g_psq[C_ROWS];   // ||p||^2 exact
__device__ float g_sx[N_ROWS];    // 2 * amax_x / 448
__device__ float g_sp[C_ROWS];    //     amax_r / 448

// ------------------------------ helpers ------------------------------------
__device__ __forceinline__ uint32_t s2u(const void* p) {
    return (uint32_t)__cvta_generic_to_shared(p);
}
__device__ __forceinline__ uint32_t swz(uint32_t o) { return o ^ ((o >> 3) & 0x70u); }

__device__ __forceinline__ void mbar_init(uint32_t a, uint32_t n) {
    asm volatile("mbarrier.init.shared.b64 [%0], %1;" :: "r"(a), "r"(n) : "memory");
}
__device__ __forceinline__ void mbar_expect(uint32_t a, uint32_t tx) {
    asm volatile("mbarrier.arrive.expect_tx.shared.b64 _, [%0], %1;"
                 :: "r"(a), "r"(tx) : "memory");
}
__device__ __forceinline__ void mbar_arrive(uint32_t a) {
    asm volatile("mbarrier.arrive.shared.b64 _, [%0];" :: "r"(a) : "memory");
}
__device__ __forceinline__ void mbar_wait(uint32_t a, uint32_t phase) {
    asm volatile(
        "{\n\t.reg .pred P;\n"
        "W%=:\n\t"
        "mbarrier.try_wait.parity.acquire.cta.shared::cta.b64 P, [%0], %1, 0x989680;\n\t"
        "@P bra D%=;\n\t"
        "bra W%=;\n"
        "D%=:\n\t}"
        :: "r"(a), "r"(phase) : "memory");
}
__device__ __forceinline__ void bulk_g2s(uint32_t dst, const void* src,
                                         uint32_t bytes, uint32_t bar) {
    asm volatile(
        "cp.async.bulk.shared::cluster.global.mbarrier::complete_tx::bytes "
        "[%0], [%1], %2, [%3];"
        :: "r"(dst), "l"(src), "r"(bytes), "r"(bar) : "memory");
}
__device__ __forceinline__ void ldm_x4(uint32_t* r, uint32_t addr) {
    asm volatile("ldmatrix.sync.aligned.m8n8.x4.shared.b16 {%0,%1,%2,%3}, [%4];"
                 : "=r"(r[0]), "=r"(r[1]), "=r"(r[2]), "=r"(r[3]) : "r"(addr));
}
__device__ __forceinline__ void mma16832(float* c, const uint32_t* a,
                                         uint32_t b0, uint32_t b1) {
    asm volatile(
        "mma.sync.aligned.m16n8k32.row.col.f32.e4m3.e4m3.f32 "
        "{%0,%1,%2,%3}, {%4,%5,%6,%7}, {%8,%9}, {%0,%1,%2,%3};"
        : "+f"(c[0]), "+f"(c[1]), "+f"(c[2]), "+f"(c[3])
        : "r"(a[0]), "r"(a[1]), "r"(a[2]), "r"(a[3]), "r"(b0), "r"(b1));
}
__device__ __forceinline__ uint32_t qfp8x4(float4 f, float q) {
    __nv_fp8x4_e4m3 v(make_float4(f.x * q, f.y * q, f.z * q, f.w * q));
    return *reinterpret_cast<uint32_t*>(&v);
}

// ------ pre-pass: f32 -> scaled e4m3, TILED+SWIZZLED blocks + norms --------
__global__ void __launch_bounds__(128)
convq_kernel(const float* __restrict__ xsrc, const float* __restrict__ psrc) {
    const bool isx = (blockIdx.x < N_ROWS / 4);
    const int row  = (isx ? blockIdx.x : blockIdx.x - N_ROWS / 4) * 4
                   + (threadIdx.x >> 5);
    const int lane = threadIdx.x & 31;
    const float* src = isx ? xsrc : psrc;
    uint8_t* dst     = isx ? g_A : g_B;
    const float4* xr = reinterpret_cast<const float4*>(src + (size_t)row * DDIM);

    float4 f[2][4];
    float ss = 0.f, sm = 0.f, am = 0.f;
#pragma unroll
    for (int h = 0; h < 2; h++) {
        const int c = lane + h * 32;
#pragma unroll
        for (int j = 0; j < 4; j++) {
            float4 v = xr[c * 4 + j];
            ss += v.x * v.x + v.y * v.y + v.z * v.z + v.w * v.w;
            if (isx) {
                sm += v.x + v.y + v.z + v.w;
            } else {
                v.x -= 0.5f; v.y -= 0.5f; v.z -= 0.5f; v.w -= 0.5f;
            }
            f[h][j] = v;
            am = fmaxf(am, fmaxf(fmaxf(fabsf(v.x), fabsf(v.y)),
                                 fmaxf(fabsf(v.z), fabsf(v.w))));
        }
    }
#pragma unroll
    for (int o = 16; o; o >>= 1) {
        ss += __shfl_xor_sync(0xffffffffu, ss, o);
        am = fmaxf(am, __shfl_xor_sync(0xffffffffu, am, o));
        sm += __shfl_xor_sync(0xffffffffu, sm, o);
    }
    am = fmaxf(am, 1e-30f);
    const float q = 448.f / am;

    const int rt = row >> 7, rr = row & 127;
#pragma unroll
    for (int h = 0; h < 2; h++) {
        const int c  = lane + h * 32;
        const int kt = c >> 3;
        const int cu = (c & 7) * 16;
        uint4 v;
        v.x = qfp8x4(f[h][0], q); v.y = qfp8x4(f[h][1], q);
        v.z = qfp8x4(f[h][2], q); v.w = qfp8x4(f[h][3], q);
        uint8_t* blk = dst + ((size_t)rt * K_TILES + kt) * BLOCK_BYTES;
        *reinterpret_cast<uint4*>(blk + swz((uint32_t)(rr * 128 + cu))) = v;
    }
    if (lane == 0) {
        if (isx) {
            g_xc[row] = ss - sm;
            g_sx[row] = 2.f * am * (1.f / 448.f);
        } else {
            g_psq[row] = ss;
            g_sp[row]  = am * (1.f / 448.f);
        }
    }
}

// --------------------------- main GEMM kernel ------------------------------
// CTA: 256 threads = 8 warps (2M x 4N); warp tile 64x32; 2 CTAs/SM.
__global__ void __launch_bounds__(256, 2)
gemm_kernel(float* __restrict__ out) {
    extern __shared__ char smem[];
    __shared__ __align__(8) uint64_t s_bar[2 * STAGES];   // FULL[3], EMPTY[3]

    const uint32_t sbase = (s2u(smem) + 1023u) & ~1023u;
    const uint32_t FULL  = s2u(s_bar);
    const uint32_t EMPTY = FULL + STAGES * 8;

    const int tid  = threadIdx.x;
    const int wid  = tid >> 5;
    const int lane = tid & 31;
    const int wm = (wid & 1) * 64;
    const int wn = (wid >> 1) * 32;

    const uint8_t* Ag = g_A + (size_t)blockIdx.x * K_TILES * BLOCK_BYTES;
    const uint8_t* Bg = g_B + (size_t)blockIdx.y * K_TILES * BLOCK_BYTES;

    if (tid == 0) {
#pragma unroll
        for (int s = 0; s < STAGES; s++) {
            mbar_init(FULL + s * 8, 1);            // tx-based completion
            mbar_init(EMPTY + s * 8, 8);           // one arrive per warp
        }
    }
    __syncthreads();

    if (tid == 0) {
#pragma unroll
        for (int s = 0; s < STAGES - 1; s++) {
            const uint32_t fb  = FULL + s * 8;
            const uint32_t dst = sbase + s * STAGE_BYTES;
            mbar_expect(fb, STAGE_BYTES);
            bulk_g2s(dst,               Ag + (size_t)s * BLOCK_BYTES, BLOCK_BYTES, fb);
            bulk_g2s(dst + BLOCK_BYTES, Bg + (size_t)s * BLOCK_BYTES, BLOCK_BYTES, fb);
        }
    }

    float acc[4][4][4];
#pragma unroll
    for (int i = 0; i < 4; i++)
#pragma unroll
        for (int j = 0; j < 4; j++)
#pragma unroll
            for (int r = 0; r < 4; r++) acc[i][j][r] = 0.f;

    const int lrow = lane & 15;
    const int lkb  = (lane >> 4) * 16;

    // precomputed swizzle-invariant address parts
    // addr(row, kc) = base + row*128 + (kc ^ ((row&7)*16))
    uint32_t arow[4], axor[4], brow[2], bxor[2];
#pragma unroll
    for (int mi = 0; mi < 4; mi++) {
        const int r = wm + mi * 16 + lrow;
        arow[mi] = (uint32_t)(r * 128);
        axor[mi] = (uint32_t)((r & 7) * 16);
    }
#pragma unroll
    for (int nj = 0; nj < 2; nj++) {
        const int r = wn + nj * 16 + lrow;
        brow[nj] = (uint32_t)(r * 128);
        bxor[nj] = (uint32_t)((r & 7) * 16);
    }

    uint32_t a[4][4];       // A fragments, one kk deep (reloaded per kk)
    uint32_t b[2][2][4];    // B fragments, double-buffered across kk

    int pst = STAGES - 1, pph = 1;                 // producer cursor
    int cst = 0, cph = 0;                          // consumer cursor

    for (int kt = 0; kt < K_TILES; kt++) {
        // ---- producer: refill stage for kt+STAGES-1 ----------------------
        if (tid == 0 && kt + STAGES - 1 < K_TILES) {
            const int kf = kt + STAGES - 1;
            mbar_wait(EMPTY + pst * 8, (uint32_t)pph);
            const uint32_t fb  = FULL + pst * 8;
            const uint32_t dst = sbase + pst * STAGE_BYTES;
            mbar_expect(fb, STAGE_BYTES);
            bulk_g2s(dst,               Ag + (size_t)kf * BLOCK_BYTES, BLOCK_BYTES, fb);
            bulk_g2s(dst + BLOCK_BYTES, Bg + (size_t)kf * BLOCK_BYTES, BLOCK_BYTES, fb);
            if (++pst == STAGES) { pst = 0; pph ^= 1; }
        }

        // ---- consumer: interleaved [ldm][mma] stream ---------------------
        mbar_wait(FULL + cst * 8, (uint32_t)cph);
        const uint32_t sA = sbase + cst * STAGE_BYTES;
        const uint32_t sB = sA + BLOCK_BYTES;

        // prime: B fragments for kk=0
        {
            const uint32_t kc = (uint32_t)lkb;
            ldm_x4(b[0][0], sB + brow[0] + (kc ^ bxor[0]));
            ldm_x4(b[0][1], sB + brow[1] + (kc ^ bxor[1]));
        }

#pragma unroll
        for (int kk = 0; kk < 4; kk++) {
            const int cur = kk & 1;
            const uint32_t kc  = (uint32_t)(kk * 32 + lkb);
            const uint32_t kcn = (uint32_t)((kk + 1) * 32 + lkb);

            ldm_x4(a[0], sA + arow[0] + (kc ^ axor[0]));
#pragma unroll
            for (int mi = 0; mi < 4; mi++) {
                if (mi < 3) {
                    ldm_x4(a[mi + 1], sA + arow[mi + 1] + (kc ^ axor[mi + 1]));
                } else if (kk < 3) {
                    const int nxt = cur ^ 1;
                    ldm_x4(b[nxt][0], sB + brow[0] + (kcn ^ bxor[0]));
                    ldm_x4(b[nxt][1], sB + brow[1] + (kcn ^ bxor[1]));
                } else if (lane == 0) {
                    mbar_arrive(EMPTY + cst * 8);  // last smem reads issued
                }
#pragma unroll
                for (int nj = 0; nj < 2; nj++) {
                    mma16832(acc[mi][2 * nj + 0], a[mi],
                             b[cur][nj][0], b[cur][nj][2]);
                    mma16832(acc[mi][2 * nj + 1], a[mi],
                             b[cur][nj][1], b[cur][nj][3]);
                }
            }
        }
        if (++cst == STAGES) { cst = 0; cph ^= 1; }
    }

    // ---- fused dequant epilogue: out = xc + psq - sx*sp*acc  (x2 in sx) ----
    const int m0 = blockIdx.x * TILE_M;
    const int n0 = blockIdx.y * TILE_N;
    const int tr = lane >> 2;
    const int tc = (lane & 3) * 2;
#pragma unroll
    for (int mi = 0; mi < 4; mi++) {
        const int gm0 = m0 + wm + mi * 16 + tr;
        const float xc0 = g_xc[gm0],     sx0 = g_sx[gm0];
        const float xc1 = g_xc[gm0 + 8], sx1 = g_sx[gm0 + 8];
        float* o0 = out + (size_t)gm0 * C_ROWS + n0 + wn;
        float* o1 = o0 + (size_t)8 * C_ROWS;
#pragma unroll
        for (int ni = 0; ni < 4; ni++) {
            const int gc = n0 + wn + ni * 8 + tc;
            const float pq0 = __ldg(g_psq + gc),     sp0 = __ldg(g_sp + gc);
            const float pq1 = __ldg(g_psq + gc + 1), sp1 = __ldg(g_sp + gc + 1);
            float2 r0, r1;
            r0.x = fmaf(-sx0 * sp0, acc[mi][ni][0], xc0 + pq0);
            r0.y = fmaf(-sx0 * sp1, acc[mi][ni][1], xc0 + pq1);
            r1.x = fmaf(-sx1 * sp0, acc[mi][ni][2], xc1 + pq0);
            r1.y = fmaf(-sx1 * sp1, acc[mi][ni][3], xc1 + pq1);
            *reinterpret_cast<float2*>(o0 + ni * 8 + tc) = r0;
            *reinterpret_cast<float2*>(o1 + ni * 8 + tc) = r1;
        }
    }
}

// ------------------------------- launch ------------------------------------
extern "C" void kernel_launch(void* const* d_in, const int* in_sizes, int n_in,
                              void* d_out, int out_size) {
    const float* x = (const float*)d_in[0];       // [16384, 1024]
    const float* p = (const float*)d_in[1];       // [4096, 1024]
    float* out = (float*)d_out;                   // [16384, 4096]

    cudaFuncSetAttribute(gemm_kernel,
                         cudaFuncAttributeMaxDynamicSharedMemorySize, SMEM_DYN);

    convq_kernel<<<(N_ROWS + C_ROWS) / 4, 128>>>(x, p);
    gemm_kernel<<<dim3(N_ROWS / TILE_M, C_ROWS / TILE_N), 256, SMEM_DYN>>>(out);
}